// round 3
// baseline (speedup 1.0000x reference)
#include <cuda_runtime.h>

#define NN     8192
#define KP1    4096
#define KP2    2048
#define FF     32
#define FIN    16
#define MAXDEG 256
#define SUBMAX 192
#define FULLMASK 0xffffffffu

// ---------------- device scratch (static globals; no allocations) -------------
__device__ int    g_rowcnt[NN];
__device__ int    g_cols[NN * MAXDEG];       // padded CSR, rowstart = row*MAXDEG
__device__ int    g_subcnt[KP1];
__device__ int    g_subcols[KP1 * SUBMAX];   // rank-remapped sub CSR
__device__ float  g_dinv[NN];
__device__ float  g_dinvs[KP1];
__device__ float  g_G1[NN * FF];
__device__ float  g_X1[NN * FF];
__device__ float  g_G2[KP1 * FF];
__device__ float  g_X2[KP1 * FF];
__device__ float  g_G3[KP1 * FF];
__device__ float  g_X3[KP1 * FF];
__device__ float2 g_G4[NN];
__device__ float  g_score1[NN];
__device__ float  g_score2[KP1];
__device__ int    g_rank1[NN];
__device__ int    g_rank2[KP1];
__device__ int    g_idx1[KP1];
__device__ int    g_idx2[KP2];

// ---------------- CSR build + dinv + G1 (fused) --------------------------------
__global__ void k_csr_g1(const float* __restrict__ A,
                         const float* __restrict__ x,
                         const float* __restrict__ W1) {
    int row = blockIdx.x;
    int t   = threadIdx.x;
    int lane = t & 31, wid = t >> 5;

    __shared__ float w1s[FIN * FF];
    __shared__ int   wtot[8];
    __shared__ int   wbase[8];
    __shared__ int   stot;

    if (t < FIN * FF / 2) {            // 512 floats, 2 per thread
        w1s[t]       = W1[t];
        w1s[t + 256] = W1[t + 256];
    }

    const float4* ar = reinterpret_cast<const float4*>(A + (size_t)row * NN);
    float4 v[8];
    int c = 0;
#pragma unroll
    for (int k = 0; k < 8; k++) {
        v[k] = __ldcs(ar + k * 256 + t);
        c += (v[k].x != 0.f) + (v[k].y != 0.f) + (v[k].z != 0.f) + (v[k].w != 0.f);
    }

    int inc = c;
#pragma unroll
    for (int o = 1; o < 32; o <<= 1) {
        int y = __shfl_up_sync(FULLMASK, inc, o);
        if (lane >= o) inc += y;
    }
    if (lane == 31) wtot[wid] = inc;
    __syncthreads();
    if (t == 0) {
        int s = 0;
#pragma unroll
        for (int i = 0; i < 8; i++) { wbase[i] = s; s += wtot[i]; }
        stot = s;
        g_rowcnt[row] = (s < MAXDEG) ? s : MAXDEG;
        g_dinv[row]   = rsqrtf((float)s + 1.0f + 1e-10f);
    }
    __syncthreads();

    int off = wbase[wid] + inc - c;
    int* cp = g_cols + row * MAXDEG;
#pragma unroll
    for (int k = 0; k < 8; k++) {
        int col0 = (k * 256 + t) * 4;
        if (v[k].x != 0.f) { if (off < MAXDEG) cp[off] = col0 + 0; off++; }
        if (v[k].y != 0.f) { if (off < MAXDEG) cp[off] = col0 + 1; off++; }
        if (v[k].z != 0.f) { if (off < MAXDEG) cp[off] = col0 + 2; off++; }
        if (v[k].w != 0.f) { if (off < MAXDEG) cp[off] = col0 + 3; off++; }
    }

    if (wid == 0) {
        float d  = rsqrtf((float)stot + 1.0f + 1e-10f);
        float xv = (lane < FIN) ? x[row * FIN + lane] : 0.f;
        float acc = 0.f;
#pragma unroll
        for (int f = 0; f < FIN; f++) {
            float xf = __shfl_sync(FULLMASK, xv, f);
            acc += xf * w1s[f * FF + lane];
        }
        g_G1[row * FF + lane] = d * acc;
    }
}

// ---------------- main SpMM: X1 = relu(dinv*(A_hat @ G1)); score1 --------------
__global__ void k_spmm_main(const float* __restrict__ s1) {
    __shared__ float sv[FF];
    if (threadIdx.x < FF) sv[threadIdx.x] = s1[threadIdx.x];
    __syncthreads();
    int warp = (blockIdx.x * blockDim.x + threadIdx.x) >> 5;
    int lane = threadIdx.x & 31;
    if (warp >= NN) return;
    int g = lane >> 3, fo = lane & 7;
    int cnt = g_rowcnt[warp];
    const int* cp = g_cols + warp * MAXDEG;
    const float4* G1v = reinterpret_cast<const float4*>(g_G1);

    // preload all column chunks (max 8) into registers: high MLP
    int mycol[8];
    int nch = (cnt + 31) >> 5;
#pragma unroll
    for (int c = 0; c < 8; c++) {
        int kc = c * 32 + lane;
        mycol[c] = (c < nch && kc < cnt) ? cp[kc] : -1;
    }

    float4 acc = make_float4(0.f, 0.f, 0.f, 0.f);
    if (g == 0) acc = G1v[warp * 8 + fo];    // identity (+I) term
#pragma unroll
    for (int ch = 0; ch < 8; ch++) {
        if (ch >= nch) break;
#pragma unroll
        for (int s = 0; s < 8; s++) {
            int c = __shfl_sync(FULLMASK, mycol[ch], s * 4 + g);
            if (c >= 0) {
                float4 tv = G1v[c * 8 + fo];
                acc.x += tv.x; acc.y += tv.y; acc.z += tv.z; acc.w += tv.w;
            }
        }
    }
#pragma unroll
    for (int o = 8; o <= 16; o <<= 1) {
        acc.x += __shfl_xor_sync(FULLMASK, acc.x, o);
        acc.y += __shfl_xor_sync(FULLMASK, acc.y, o);
        acc.z += __shfl_xor_sync(FULLMASK, acc.z, o);
        acc.w += __shfl_xor_sync(FULLMASK, acc.w, o);
    }
    float d = g_dinv[warp];
    acc.x = fmaxf(d * acc.x, 0.f); acc.y = fmaxf(d * acc.y, 0.f);
    acc.z = fmaxf(d * acc.z, 0.f); acc.w = fmaxf(d * acc.w, 0.f);
    if (g == 0) reinterpret_cast<float4*>(g_X1)[warp * 8 + fo] = acc;

    float s = acc.x * sv[fo * 4 + 0] + acc.y * sv[fo * 4 + 1] +
              acc.z * sv[fo * 4 + 2] + acc.w * sv[fo * 4 + 3];
    s += __shfl_down_sync(FULLMASK, s, 4);
    s += __shfl_down_sync(FULLMASK, s, 2);
    s += __shfl_down_sync(FULLMASK, s, 1);
    if (lane == 0) g_score1[warp] = s;
}

// ---------------- exact top-K set (radix select, warp-aggregated hist) ---------
__global__ void k_topk(int which) {
    const float* scores = which ? g_score2 : g_score1;
    int  n        = which ? KP1 : NN;
    int  K        = which ? KP2 : KP1;
    int* idx_out  = which ? g_idx2 : g_idx1;
    int* rank_out = which ? g_rank2 : g_rank1;

    __shared__ unsigned su[NN];
    __shared__ int hist[256];
    __shared__ int wagg[32];
    __shared__ int sh_prefix, sh_need;

    int t = threadIdx.x;
    int lane = t & 31, wid = t >> 5;
    int seg = n >> 10;                       // 8 or 4 contiguous elems per thread

    for (int i = t; i < n; i += 1024) {
        unsigned b = __float_as_uint(scores[i]);
        su[i] = (b & 0x80000000u) ? ~b : (b | 0x80000000u);
    }
    if (t == 0) { sh_prefix = 0; sh_need = K; }
    __syncthreads();

    for (int shift = 24; shift >= 0; shift -= 8) {
        if (t < 256) hist[t] = 0;
        __syncthreads();
        unsigned pfx = (unsigned)sh_prefix;
        for (int j = 0; j < seg; j++) {
            unsigned u = su[t * seg + j];
            bool match = (shift == 24) ||
                         ((u >> (shift + 8)) == (pfx >> (shift + 8)));
            int bin = match ? (int)((u >> shift) & 255) : 300;  // 300 = skip
            // warp-aggregated atomic: one ATOMS per distinct bin per warp
            unsigned mm = __match_any_sync(FULLMASK, bin);
            int leader = __ffs(mm) - 1;
            if (lane == leader && bin < 256) atomicAdd(&hist[bin], __popc(mm));
        }
        __syncthreads();
        if (t == 0) {
            int need = sh_need;
            int b = 255;
            while (b > 0 && hist[b] < need) { need -= hist[b]; b--; }
            sh_prefix = (int)(pfx | ((unsigned)b << shift));
            sh_need = need;
        }
        __syncthreads();
    }
    unsigned T = (unsigned)sh_prefix;        // exact K-th largest key
    int need_eq = sh_need;                   // #(==T) to take, lowest indices

    int gt = 0, eq = 0;
    for (int j = 0; j < seg; j++) {
        unsigned u = su[t * seg + j];
        gt += (u > T); eq += (u == T);
    }
    int packed = (gt << 16) | eq;
    int s = packed;
#pragma unroll
    for (int o = 1; o < 32; o <<= 1) {
        int y = __shfl_up_sync(FULLMASK, s, o);
        if (lane >= o) s += y;
    }
    if (lane == 31) wagg[wid] = s;
    __syncthreads();
    if (wid == 0) {
        int w = wagg[lane];
#pragma unroll
        for (int o = 1; o < 32; o <<= 1) {
            int y = __shfl_up_sync(FULLMASK, w, o);
            if (lane >= o) w += y;
        }
        wagg[lane] = w;
    }
    __syncthreads();
    int excl = s - packed + (wid ? wagg[wid - 1] : 0);
    int gtb = excl >> 16, eqb = excl & 0xffff;

    for (int j = 0; j < seg; j++) {
        int i = t * seg + j;
        unsigned u = su[i];
        bool isgt = (u > T), iseq = (u == T);
        bool sel  = isgt || (iseq && eqb < need_eq);
        int taken_eq = (eqb < need_eq) ? eqb : need_eq;
        int pos = gtb + taken_eq;
        if (sel) { rank_out[i] = pos; idx_out[pos] = i; }
        else       rank_out[i] = -1;
        gtb += isgt; eqb += iseq;
    }
}

// ---------------- sub-CSR build + dinvs + G2 (fused, batched MLP) --------------
__global__ void k_sub(const float* __restrict__ W2) {
    __shared__ float w[FF * FF];
    for (int i = threadIdx.x; i < FF * FF; i += blockDim.x) w[i] = W2[i];
    __syncthreads();
    int r = (blockIdx.x * blockDim.x + threadIdx.x) >> 5;
    int lane = threadIdx.x & 31;
    if (r >= KP1) return;
    int i = g_idx1[r];
    int cnt = g_rowcnt[i];
    const int* cp = g_cols + i * MAXDEG;
    int* sp = g_subcols + r * SUBMAX;
    unsigned lt = (1u << lane) - 1u;
    int nch = (cnt + 31) >> 5;

    // batch-load cols, then ranks (all independent -> one latency wall each)
    int col[8], rk[8];
#pragma unroll
    for (int c = 0; c < 8; c++) {
        int k = c * 32 + lane;
        col[c] = (c < nch && k < cnt) ? cp[k] : -1;
    }
#pragma unroll
    for (int c = 0; c < 8; c++)
        rk[c] = (col[c] >= 0) ? g_rank1[col[c]] : -1;

    int wcnt = 0;
#pragma unroll
    for (int c = 0; c < 8; c++) {
        if (c >= nch) break;
        int ok = (rk[c] >= 0);
        unsigned m = __ballot_sync(FULLMASK, ok);
        if (ok) { int p = wcnt + __popc(m & lt); if (p < SUBMAX) sp[p] = rk[c]; }
        wcnt += __popc(m);
    }
    float di = rsqrtf((float)wcnt + 1.0f + 1e-10f);
    if (lane == 0) {
        g_subcnt[r] = (wcnt < SUBMAX) ? wcnt : SUBMAX;
        g_dinvs[r]  = di;
    }
    float xv = g_X1[i * FF + lane];
    float acc = 0.f;
#pragma unroll
    for (int f = 0; f < FF; f++) {
        float xf = __shfl_sync(FULLMASK, xv, f);
        acc += xf * w[f * FF + lane];
    }
    g_G2[r * FF + lane] = di * acc;
}

// ---------------- subgraph SpMM (vectorized, pre-filtered sub-CSR) -------------
__global__ void k_spmm_sub(int phase, const float* __restrict__ svec) {
    __shared__ float sv[FF];
    if (phase == 0 && threadIdx.x < FF) sv[threadIdx.x] = svec[threadIdx.x];
    __syncthreads();
    const float4* Gv = reinterpret_cast<const float4*>(phase ? g_G3 : g_G2);
    float4*       Xv = reinterpret_cast<float4*>(phase ? g_X3 : g_X2);
    int r = (blockIdx.x * blockDim.x + threadIdx.x) >> 5;
    int lane = threadIdx.x & 31;
    if (r >= KP1) return;
    int g = lane >> 3, fo = lane & 7;
    int cnt = g_subcnt[r];
    const int* sp = g_subcols + r * SUBMAX;
    int nch = (cnt + 31) >> 5;

    int mycol[6];
#pragma unroll
    for (int c = 0; c < 6; c++) {
        int kc = c * 32 + lane;
        mycol[c] = (c < nch && kc < cnt) ? sp[kc] : -1;
    }

    float4 acc = make_float4(0.f, 0.f, 0.f, 0.f);
    if (g == 0) acc = Gv[r * 8 + fo];
#pragma unroll
    for (int ch = 0; ch < 6; ch++) {
        if (ch >= nch) break;
#pragma unroll
        for (int s = 0; s < 8; s++) {
            int c = __shfl_sync(FULLMASK, mycol[ch], s * 4 + g);
            if (c >= 0) {
                float4 tv = Gv[c * 8 + fo];
                acc.x += tv.x; acc.y += tv.y; acc.z += tv.z; acc.w += tv.w;
            }
        }
    }
#pragma unroll
    for (int o = 8; o <= 16; o <<= 1) {
        acc.x += __shfl_xor_sync(FULLMASK, acc.x, o);
        acc.y += __shfl_xor_sync(FULLMASK, acc.y, o);
        acc.z += __shfl_xor_sync(FULLMASK, acc.z, o);
        acc.w += __shfl_xor_sync(FULLMASK, acc.w, o);
    }
    float d = g_dinvs[r];
    acc.x = fmaxf(d * acc.x, 0.f); acc.y = fmaxf(d * acc.y, 0.f);
    acc.z = fmaxf(d * acc.z, 0.f); acc.w = fmaxf(d * acc.w, 0.f);
    if (g == 0) Xv[r * 8 + fo] = acc;
    if (phase == 0) {
        float s = acc.x * sv[fo * 4 + 0] + acc.y * sv[fo * 4 + 1] +
                  acc.z * sv[fo * 4 + 2] + acc.w * sv[fo * 4 + 3];
        s += __shfl_down_sync(FULLMASK, s, 4);
        s += __shfl_down_sync(FULLMASK, s, 2);
        s += __shfl_down_sync(FULLMASK, s, 1);
        if (lane == 0) g_score2[r] = s;
    }
}

// ---------------- G3 = (rank2>=0) ? dinvs*(X2@W3) : 0 --------------------------
__global__ void k_g3(const float* __restrict__ W3) {
    __shared__ float w[FF * FF];
    for (int i = threadIdx.x; i < FF * FF; i += blockDim.x) w[i] = W3[i];
    __syncthreads();
    int r = (blockIdx.x * blockDim.x + threadIdx.x) >> 5;
    int lane = threadIdx.x & 31;
    if (r >= KP1) return;
    if (g_rank2[r] < 0) { g_G3[r * FF + lane] = 0.f; return; }
    float xv = g_X2[r * FF + lane];
    float acc = 0.f;
#pragma unroll
    for (int f = 0; f < FF; f++) {
        float xf = __shfl_sync(FULLMASK, xv, f);
        acc += xf * w[f * FF + lane];
    }
    g_G3[r * FF + lane] = g_dinvs[r] * acc;
}

// ---------------- G4 = dinv * (unpool1(X3) @ W4) -------------------------------
__global__ void k_g4(const float* __restrict__ W4) {
    __shared__ float w[FF * 2];
    for (int i = threadIdx.x; i < FF * 2; i += blockDim.x) w[i] = W4[i];
    __syncthreads();
    int i = blockIdx.x * blockDim.x + threadIdx.x;
    if (i >= NN) return;
    int rr = g_rank1[i];
    float h0 = 0.f, h1 = 0.f;
    if (rr >= 0) {
        const float4* xr = reinterpret_cast<const float4*>(g_X3 + rr * FF);
#pragma unroll
        for (int q = 0; q < 8; q++) {
            float4 xv = xr[q];
            h0 += xv.x * w[(q * 4 + 0) * 2] + xv.y * w[(q * 4 + 1) * 2] +
                  xv.z * w[(q * 4 + 2) * 2] + xv.w * w[(q * 4 + 3) * 2];
            h1 += xv.x * w[(q * 4 + 0) * 2 + 1] + xv.y * w[(q * 4 + 1) * 2 + 1] +
                  xv.z * w[(q * 4 + 2) * 2 + 1] + xv.w * w[(q * 4 + 3) * 2 + 1];
        }
    }
    float d = g_dinv[i];
    g_G4[i] = make_float2(d * h0, d * h1);
}

// ---------------- final SpMM (F=2) + normalization + softmax -------------------
__global__ void k_final(float* __restrict__ out) {
    int warp = (blockIdx.x * blockDim.x + threadIdx.x) >> 5;
    int lane = threadIdx.x & 31;
    if (warp >= NN) return;
    int cnt = g_rowcnt[warp];
    const int* cp = g_cols + warp * MAXDEG;
    int nch = (cnt + 31) >> 5;

    int col[8];
#pragma unroll
    for (int c = 0; c < 8; c++) {
        int k = c * 32 + lane;
        col[c] = (c < nch && k < cnt) ? cp[k] : -1;
    }
    float a0 = 0.f, a1 = 0.f;
#pragma unroll
    for (int c = 0; c < 8; c++) {
        if (col[c] >= 0) {
            float2 gv = g_G4[col[c]];
            a0 += gv.x; a1 += gv.y;
        }
    }
#pragma unroll
    for (int o = 16; o > 0; o >>= 1) {
        a0 += __shfl_down_sync(FULLMASK, a0, o);
        a1 += __shfl_down_sync(FULLMASK, a1, o);
    }
    if (lane == 0) {
        float2 gs = g_G4[warp];
        float d = g_dinv[warp];
        float y0 = d * (a0 + gs.x);
        float y1 = d * (a1 + gs.y);
        float m = fmaxf(y0, y1);
        float e0 = expf(y0 - m);
        float e1 = expf(y1 - m);
        float inv = 1.0f / (e0 + e1);
        out[warp * 2 + 0] = e0 * inv;
        out[warp * 2 + 1] = e1 * inv;
    }
}

// ---------------- launcher ----------------------------------------------------
extern "C" void kernel_launch(void* const* d_in, const int* in_sizes, int n_in,
                              void* d_out, int out_size) {
    (void)in_sizes; (void)n_in; (void)out_size;
    const float* x  = (const float*)d_in[0];
    const float* a  = (const float*)d_in[1];
    const float* W1 = (const float*)d_in[2];
    const float* W2 = (const float*)d_in[3];
    const float* W3 = (const float*)d_in[4];
    const float* W4 = (const float*)d_in[5];
    const float* s1 = (const float*)d_in[6];
    const float* s2 = (const float*)d_in[7];
    float* out = (float*)d_out;

    k_csr_g1<<<NN, 256>>>(a, x, W1);
    k_spmm_main<<<NN / 8, 256>>>(s1);
    k_topk<<<1, 1024>>>(0);
    k_sub<<<KP1 / 8, 256>>>(W2);
    k_spmm_sub<<<KP1 / 8, 256>>>(0, s2);
    k_topk<<<1, 1024>>>(1);
    k_g3<<<KP1 / 8, 256>>>(W3);
    k_spmm_sub<<<KP1 / 8, 256>>>(1, nullptr);
    k_g4<<<NN / 256, 256>>>(W4);
    k_final<<<NN / 8, 256>>>(out);
}

// round 4
// speedup vs baseline: 1.0343x; 1.0343x over previous
#include <cuda_runtime.h>

#define NN     8192
#define KP1    4096
#define KP2    2048
#define FF     32
#define FIN    16
#define MAXDEG 256
#define SUBMAX 192
#define FULLMASK 0xffffffffu

// ---------------- device scratch (static globals; no allocations) -------------
__device__ int    g_rowcnt[NN];
__device__ int    g_cols[NN * MAXDEG];       // padded CSR, rowstart = row*MAXDEG
__device__ int    g_subcnt[KP1];
__device__ int    g_subcols[KP1 * SUBMAX];   // rank-remapped sub CSR
__device__ float  g_dinv[NN];
__device__ float  g_dinvs[KP1];
__device__ float  g_G1[NN * FF];
__device__ float  g_X1[NN * FF];
__device__ float  g_G2[KP1 * FF];
__device__ float  g_X2[KP1 * FF];
__device__ float  g_G3[KP1 * FF];
__device__ float  g_X3[KP1 * FF];
__device__ float2 g_G4[NN];
__device__ float  g_score1[NN];
__device__ float  g_score2[KP1];
__device__ int    g_rank1[NN];
__device__ int    g_rank2[KP1];
__device__ int    g_idx1[KP1];
__device__ int    g_idx2[KP2];

// ---------------- CSR build + dinv + G1 (fused) --------------------------------
__global__ void k_csr_g1(const float* __restrict__ A,
                         const float* __restrict__ x,
                         const float* __restrict__ W1) {
    int row = blockIdx.x;
    int t   = threadIdx.x;
    int lane = t & 31, wid = t >> 5;

    __shared__ float w1s[FIN * FF];
    __shared__ int   wtot[8];
    __shared__ int   wbase[8];
    __shared__ int   stot;

    if (t < FIN * FF / 2) {            // 512 floats, 2 per thread
        w1s[t]       = W1[t];
        w1s[t + 256] = W1[t + 256];
    }

    const float4* ar = reinterpret_cast<const float4*>(A + (size_t)row * NN);
    float4 v[8];
    int c = 0;
#pragma unroll
    for (int k = 0; k < 8; k++) {
        v[k] = __ldcs(ar + k * 256 + t);
        c += (v[k].x != 0.f) + (v[k].y != 0.f) + (v[k].z != 0.f) + (v[k].w != 0.f);
    }

    int inc = c;
#pragma unroll
    for (int o = 1; o < 32; o <<= 1) {
        int y = __shfl_up_sync(FULLMASK, inc, o);
        if (lane >= o) inc += y;
    }
    if (lane == 31) wtot[wid] = inc;
    __syncthreads();
    if (t == 0) {
        int s = 0;
#pragma unroll
        for (int i = 0; i < 8; i++) { wbase[i] = s; s += wtot[i]; }
        stot = s;
        g_rowcnt[row] = (s < MAXDEG) ? s : MAXDEG;
        g_dinv[row]   = rsqrtf((float)s + 1.0f + 1e-10f);
    }
    __syncthreads();

    int off = wbase[wid] + inc - c;
    int* cp = g_cols + row * MAXDEG;
#pragma unroll
    for (int k = 0; k < 8; k++) {
        int col0 = (k * 256 + t) * 4;
        if (v[k].x != 0.f) { if (off < MAXDEG) cp[off] = col0 + 0; off++; }
        if (v[k].y != 0.f) { if (off < MAXDEG) cp[off] = col0 + 1; off++; }
        if (v[k].z != 0.f) { if (off < MAXDEG) cp[off] = col0 + 2; off++; }
        if (v[k].w != 0.f) { if (off < MAXDEG) cp[off] = col0 + 3; off++; }
    }

    if (wid == 0) {
        float d  = rsqrtf((float)stot + 1.0f + 1e-10f);
        float xv = (lane < FIN) ? x[row * FIN + lane] : 0.f;
        float acc = 0.f;
#pragma unroll
        for (int f = 0; f < FIN; f++) {
            float xf = __shfl_sync(FULLMASK, xv, f);
            acc += xf * w1s[f * FF + lane];
        }
        g_G1[row * FF + lane] = d * acc;
    }
}

// ---------------- main SpMM: X1 = relu(dinv*(A_hat @ G1)); score1 --------------
__global__ void k_spmm_main(const float* __restrict__ s1) {
    __shared__ float sv[FF];
    if (threadIdx.x < FF) sv[threadIdx.x] = s1[threadIdx.x];
    __syncthreads();
    int warp = (blockIdx.x * blockDim.x + threadIdx.x) >> 5;
    int lane = threadIdx.x & 31;
    if (warp >= NN) return;
    int g = lane >> 3, fo = lane & 7;
    int cnt = g_rowcnt[warp];
    const int* cp = g_cols + warp * MAXDEG;
    const float4* G1v = reinterpret_cast<const float4*>(g_G1);

    int mycol[8];
    int nch = (cnt + 31) >> 5;
#pragma unroll
    for (int c = 0; c < 8; c++) {
        int kc = c * 32 + lane;
        mycol[c] = (c < nch && kc < cnt) ? cp[kc] : -1;
    }

    float4 acc = make_float4(0.f, 0.f, 0.f, 0.f);
    if (g == 0) acc = G1v[warp * 8 + fo];    // identity (+I) term
#pragma unroll
    for (int ch = 0; ch < 8; ch++) {
        if (ch >= nch) break;
#pragma unroll
        for (int s = 0; s < 8; s++) {
            int c = __shfl_sync(FULLMASK, mycol[ch], s * 4 + g);
            if (c >= 0) {
                float4 tv = G1v[c * 8 + fo];
                acc.x += tv.x; acc.y += tv.y; acc.z += tv.z; acc.w += tv.w;
            }
        }
    }
#pragma unroll
    for (int o = 8; o <= 16; o <<= 1) {
        acc.x += __shfl_xor_sync(FULLMASK, acc.x, o);
        acc.y += __shfl_xor_sync(FULLMASK, acc.y, o);
        acc.z += __shfl_xor_sync(FULLMASK, acc.z, o);
        acc.w += __shfl_xor_sync(FULLMASK, acc.w, o);
    }
    float d = g_dinv[warp];
    acc.x = fmaxf(d * acc.x, 0.f); acc.y = fmaxf(d * acc.y, 0.f);
    acc.z = fmaxf(d * acc.z, 0.f); acc.w = fmaxf(d * acc.w, 0.f);
    if (g == 0) reinterpret_cast<float4*>(g_X1)[warp * 8 + fo] = acc;

    float s = acc.x * sv[fo * 4 + 0] + acc.y * sv[fo * 4 + 1] +
              acc.z * sv[fo * 4 + 2] + acc.w * sv[fo * 4 + 3];
    s += __shfl_down_sync(FULLMASK, s, 4);
    s += __shfl_down_sync(FULLMASK, s, 2);
    s += __shfl_down_sync(FULLMASK, s, 1);
    if (lane == 0) g_score1[warp] = s;
}

// ---------------- exact top-K set: radix select, ATOMIC-FREE histograms --------
// Keys live in registers; per-warp privatized smem histograms updated by
// match_any leaders with plain adds (no ATOMS at all on the single-SM block).
__global__ void k_topk(int which) {
    const float* scores = which ? g_score2 : g_score1;
    int  n        = which ? KP1 : NN;
    int  K        = which ? KP2 : KP1;
    int* idx_out  = which ? g_idx2 : g_idx1;
    int* rank_out = which ? g_rank2 : g_rank1;

    __shared__ int histW[32 * 256];   // per-warp private histograms (32 KB)
    __shared__ int hist[256];
    __shared__ int wagg[32];
    __shared__ int sh_prefix, sh_need;

    int t = threadIdx.x;
    int lane = t & 31, wid = t >> 5;
    int seg = n >> 10;                        // 8 (n=8192) or 4 (n=4096)

    unsigned u[8];
#pragma unroll
    for (int j = 0; j < 8; j++) {
        if (j < seg) {
            unsigned b = __float_as_uint(scores[t * seg + j]);
            u[j] = (b & 0x80000000u) ? ~b : (b | 0x80000000u);
        } else u[j] = 0u;
    }
    if (t == 0) { sh_prefix = 0; sh_need = K; }

    for (int shift = 24; shift >= 0; shift -= 8) {
        for (int i = t; i < 32 * 256; i += 1024) histW[i] = 0;
        __syncthreads();
        unsigned pfx = (unsigned)sh_prefix;
#pragma unroll
        for (int j = 0; j < 8; j++) {
            if (j >= seg) break;
            bool match = (shift == 24) ||
                         ((u[j] >> (shift + 8)) == (pfx >> (shift + 8)));
            int bin = match ? (int)((u[j] >> shift) & 255) : 300;
            unsigned mm = __match_any_sync(FULLMASK, bin);
            if (bin < 256 && lane == (__ffs(mm) - 1))
                histW[wid * 256 + bin] += __popc(mm);   // plain add, warp-private
        }
        __syncthreads();
        if (t < 256) {
            int s = 0;
#pragma unroll
            for (int w = 0; w < 32; w++) s += histW[w * 256 + t];
            hist[t] = s;
        }
        __syncthreads();
        if (t == 0) {
            int need = sh_need;
            int b = 255;
            while (b > 0 && hist[b] < need) { need -= hist[b]; b--; }
            sh_prefix = (int)(pfx | ((unsigned)b << shift));
            sh_need = need;
        }
        __syncthreads();
    }
    unsigned T = (unsigned)sh_prefix;         // exact K-th largest key
    int need_eq = sh_need;                    // #(==T) to take, lowest indices

    int gt = 0, eq = 0;
#pragma unroll
    for (int j = 0; j < 8; j++) {
        if (j >= seg) break;
        gt += (u[j] > T); eq += (u[j] == T);
    }
    int packed = (gt << 16) | eq;
    int s = packed;
#pragma unroll
    for (int o = 1; o < 32; o <<= 1) {
        int y = __shfl_up_sync(FULLMASK, s, o);
        if (lane >= o) s += y;
    }
    if (lane == 31) wagg[wid] = s;
    __syncthreads();
    if (wid == 0) {
        int w = wagg[lane];
#pragma unroll
        for (int o = 1; o < 32; o <<= 1) {
            int y = __shfl_up_sync(FULLMASK, w, o);
            if (lane >= o) w += y;
        }
        wagg[lane] = w;
    }
    __syncthreads();
    int excl = s - packed + (wid ? wagg[wid - 1] : 0);
    int gtb = excl >> 16, eqb = excl & 0xffff;

#pragma unroll
    for (int j = 0; j < 8; j++) {
        if (j >= seg) break;
        int i = t * seg + j;
        bool isgt = (u[j] > T), iseq = (u[j] == T);
        bool sel  = isgt || (iseq && eqb < need_eq);
        int taken_eq = (eqb < need_eq) ? eqb : need_eq;
        int pos = gtb + taken_eq;
        if (sel) { rank_out[i] = pos; idx_out[pos] = i; }
        else       rank_out[i] = -1;
        gtb += isgt; eqb += iseq;
    }
}

// ---------------- sub-CSR build + dinvs + G2 (fused, batched MLP) --------------
__global__ void k_sub(const float* __restrict__ W2) {
    __shared__ float w[FF * FF];
    for (int i = threadIdx.x; i < FF * FF; i += blockDim.x) w[i] = W2[i];
    __syncthreads();
    int r = (blockIdx.x * blockDim.x + threadIdx.x) >> 5;
    int lane = threadIdx.x & 31;
    if (r >= KP1) return;
    int i = g_idx1[r];
    int cnt = g_rowcnt[i];
    const int* cp = g_cols + i * MAXDEG;
    int* sp = g_subcols + r * SUBMAX;
    unsigned lt = (1u << lane) - 1u;
    int nch = (cnt + 31) >> 5;

    int col[8], rk[8];
#pragma unroll
    for (int c = 0; c < 8; c++) {
        int k = c * 32 + lane;
        col[c] = (c < nch && k < cnt) ? cp[k] : -1;
    }
#pragma unroll
    for (int c = 0; c < 8; c++)
        rk[c] = (col[c] >= 0) ? g_rank1[col[c]] : -1;

    int wcnt = 0;
#pragma unroll
    for (int c = 0; c < 8; c++) {
        if (c >= nch) break;
        int ok = (rk[c] >= 0);
        unsigned m = __ballot_sync(FULLMASK, ok);
        if (ok) { int p = wcnt + __popc(m & lt); if (p < SUBMAX) sp[p] = rk[c]; }
        wcnt += __popc(m);
    }
    float di = rsqrtf((float)wcnt + 1.0f + 1e-10f);
    if (lane == 0) {
        g_subcnt[r] = (wcnt < SUBMAX) ? wcnt : SUBMAX;
        g_dinvs[r]  = di;
    }
    float xv = g_X1[i * FF + lane];
    float acc = 0.f;
#pragma unroll
    for (int f = 0; f < FF; f++) {
        float xf = __shfl_sync(FULLMASK, xv, f);
        acc += xf * w[f * FF + lane];
    }
    g_G2[r * FF + lane] = di * acc;
}

// ---------------- subgraph SpMM (vectorized, pre-filtered sub-CSR) -------------
__global__ void k_spmm_sub(int phase, const float* __restrict__ svec) {
    __shared__ float sv[FF];
    if (phase == 0 && threadIdx.x < FF) sv[threadIdx.x] = svec[threadIdx.x];
    __syncthreads();
    const float4* Gv = reinterpret_cast<const float4*>(phase ? g_G3 : g_G2);
    float4*       Xv = reinterpret_cast<float4*>(phase ? g_X3 : g_X2);
    int r = (blockIdx.x * blockDim.x + threadIdx.x) >> 5;
    int lane = threadIdx.x & 31;
    if (r >= KP1) return;
    int g = lane >> 3, fo = lane & 7;
    int cnt = g_subcnt[r];
    const int* sp = g_subcols + r * SUBMAX;
    int nch = (cnt + 31) >> 5;

    int mycol[6];
#pragma unroll
    for (int c = 0; c < 6; c++) {
        int kc = c * 32 + lane;
        mycol[c] = (c < nch && kc < cnt) ? sp[kc] : -1;
    }

    float4 acc = make_float4(0.f, 0.f, 0.f, 0.f);
    if (g == 0) acc = Gv[r * 8 + fo];
#pragma unroll
    for (int ch = 0; ch < 6; ch++) {
        if (ch >= nch) break;
#pragma unroll
        for (int s = 0; s < 8; s++) {
            int c = __shfl_sync(FULLMASK, mycol[ch], s * 4 + g);
            if (c >= 0) {
                float4 tv = Gv[c * 8 + fo];
                acc.x += tv.x; acc.y += tv.y; acc.z += tv.z; acc.w += tv.w;
            }
        }
    }
#pragma unroll
    for (int o = 8; o <= 16; o <<= 1) {
        acc.x += __shfl_xor_sync(FULLMASK, acc.x, o);
        acc.y += __shfl_xor_sync(FULLMASK, acc.y, o);
        acc.z += __shfl_xor_sync(FULLMASK, acc.z, o);
        acc.w += __shfl_xor_sync(FULLMASK, acc.w, o);
    }
    float d = g_dinvs[r];
    acc.x = fmaxf(d * acc.x, 0.f); acc.y = fmaxf(d * acc.y, 0.f);
    acc.z = fmaxf(d * acc.z, 0.f); acc.w = fmaxf(d * acc.w, 0.f);
    if (g == 0) Xv[r * 8 + fo] = acc;
    if (phase == 0) {
        float s = acc.x * sv[fo * 4 + 0] + acc.y * sv[fo * 4 + 1] +
                  acc.z * sv[fo * 4 + 2] + acc.w * sv[fo * 4 + 3];
        s += __shfl_down_sync(FULLMASK, s, 4);
        s += __shfl_down_sync(FULLMASK, s, 2);
        s += __shfl_down_sync(FULLMASK, s, 1);
        if (lane == 0) g_score2[r] = s;
    }
}

// ---------------- G3 = (rank2>=0) ? dinvs*(X2@W3) : 0 --------------------------
__global__ void k_g3(const float* __restrict__ W3) {
    __shared__ float w[FF * FF];
    for (int i = threadIdx.x; i < FF * FF; i += blockDim.x) w[i] = W3[i];
    __syncthreads();
    int r = (blockIdx.x * blockDim.x + threadIdx.x) >> 5;
    int lane = threadIdx.x & 31;
    if (r >= KP1) return;
    if (g_rank2[r] < 0) { g_G3[r * FF + lane] = 0.f; return; }
    float xv = g_X2[r * FF + lane];
    float acc = 0.f;
#pragma unroll
    for (int f = 0; f < FF; f++) {
        float xf = __shfl_sync(FULLMASK, xv, f);
        acc += xf * w[f * FF + lane];
    }
    g_G3[r * FF + lane] = g_dinvs[r] * acc;
}

// ---------------- G4 = dinv * (unpool1(X3) @ W4) -------------------------------
__global__ void k_g4(const float* __restrict__ W4) {
    __shared__ float w[FF * 2];
    for (int i = threadIdx.x; i < FF * 2; i += blockDim.x) w[i] = W4[i];
    __syncthreads();
    int i = blockIdx.x * blockDim.x + threadIdx.x;
    if (i >= NN) return;
    int rr = g_rank1[i];
    float h0 = 0.f, h1 = 0.f;
    if (rr >= 0) {
        const float4* xr = reinterpret_cast<const float4*>(g_X3 + rr * FF);
#pragma unroll
        for (int q = 0; q < 8; q++) {
            float4 xv = xr[q];
            h0 += xv.x * w[(q * 4 + 0) * 2] + xv.y * w[(q * 4 + 1) * 2] +
                  xv.z * w[(q * 4 + 2) * 2] + xv.w * w[(q * 4 + 3) * 2];
            h1 += xv.x * w[(q * 4 + 0) * 2 + 1] + xv.y * w[(q * 4 + 1) * 2 + 1] +
                  xv.z * w[(q * 4 + 2) * 2 + 1] + xv.w * w[(q * 4 + 3) * 2 + 1];
        }
    }
    float d = g_dinv[i];
    g_G4[i] = make_float2(d * h0, d * h1);
}

// ---------------- final SpMM (F=2) + normalization + softmax -------------------
__global__ void k_final(float* __restrict__ out) {
    int warp = (blockIdx.x * blockDim.x + threadIdx.x) >> 5;
    int lane = threadIdx.x & 31;
    if (warp >= NN) return;
    int cnt = g_rowcnt[warp];
    const int* cp = g_cols + warp * MAXDEG;
    int nch = (cnt + 31) >> 5;

    int col[8];
#pragma unroll
    for (int c = 0; c < 8; c++) {
        int k = c * 32 + lane;
        col[c] = (c < nch && k < cnt) ? cp[k] : -1;
    }
    float a0 = 0.f, a1 = 0.f;
#pragma unroll
    for (int c = 0; c < 8; c++) {
        if (col[c] >= 0) {
            float2 gv = g_G4[col[c]];
            a0 += gv.x; a1 += gv.y;
        }
    }
#pragma unroll
    for (int o = 16; o > 0; o >>= 1) {
        a0 += __shfl_down_sync(FULLMASK, a0, o);
        a1 += __shfl_down_sync(FULLMASK, a1, o);
    }
    if (lane == 0) {
        float2 gs = g_G4[warp];
        float d = g_dinv[warp];
        float y0 = d * (a0 + gs.x);
        float y1 = d * (a1 + gs.y);
        float m = fmaxf(y0, y1);
        float e0 = expf(y0 - m);
        float e1 = expf(y1 - m);
        float inv = 1.0f / (e0 + e1);
        out[warp * 2 + 0] = e0 * inv;
        out[warp * 2 + 1] = e1 * inv;
    }
}

// ---------------- launcher ----------------------------------------------------
extern "C" void kernel_launch(void* const* d_in, const int* in_sizes, int n_in,
                              void* d_out, int out_size) {
    (void)in_sizes; (void)n_in; (void)out_size;
    const float* x  = (const float*)d_in[0];
    const float* a  = (const float*)d_in[1];
    const float* W1 = (const float*)d_in[2];
    const float* W2 = (const float*)d_in[3];
    const float* W3 = (const float*)d_in[4];
    const float* W4 = (const float*)d_in[5];
    const float* s1 = (const float*)d_in[6];
    const float* s2 = (const float*)d_in[7];
    float* out = (float*)d_out;

    k_csr_g1<<<NN, 256>>>(a, x, W1);
    k_spmm_main<<<NN / 8, 256>>>(s1);
    k_topk<<<1, 1024>>>(0);
    k_sub<<<KP1 / 8, 256>>>(W2);
    k_spmm_sub<<<KP1 / 8, 256>>>(0, s2);
    k_topk<<<1, 1024>>>(1);
    k_g3<<<KP1 / 8, 256>>>(W3);
    k_spmm_sub<<<KP1 / 8, 256>>>(1, nullptr);
    k_g4<<<NN / 256, 256>>>(W4);
    k_final<<<NN / 8, 256>>>(out);
}

// round 5
// speedup vs baseline: 1.1680x; 1.1293x over previous
#include <cuda_runtime.h>

#define NN     8192
#define KP1    4096
#define KP2    2048
#define FF     32
#define FIN    16
#define MAXDEG 256
#define SUBMAX 192
#define FULLMASK 0xffffffffu

// ---------------- device scratch (static globals; no allocations) -------------
__device__ int    g_rowcnt[NN];
__device__ int    g_cols[NN * MAXDEG];       // padded CSR, rowstart = row*MAXDEG
__device__ int    g_subcnt[KP1];
__device__ int    g_subcols[KP1 * SUBMAX];   // rank-remapped sub CSR
__device__ float  g_dinv[NN];
__device__ float  g_dinvs[KP1];
__device__ float  g_G1[NN * FF];
__device__ float  g_X1[NN * FF];
__device__ float  g_G2[KP1 * FF];
__device__ float  g_X2[KP1 * FF];
__device__ float  g_G3[KP1 * FF];
__device__ float  g_X3[KP1 * FF];
__device__ float2 g_G4[NN];
__device__ float  g_score1[NN];
__device__ float  g_score2[KP1];
__device__ int    g_rank1[NN];
__device__ int    g_rank2[KP1];
__device__ int    g_idx1[KP1];
__device__ int    g_idx2[KP2];

// ---------------- CSR build + dinv ---------------------------------------------
__global__ void k_csr(const float* __restrict__ A) {
    int row = blockIdx.x;
    int t   = threadIdx.x;
    int lane = t & 31, wid = t >> 5;

    __shared__ int wtot[8];
    __shared__ int wbase[8];

    const float4* ar = reinterpret_cast<const float4*>(A + (size_t)row * NN);
    float4 v[8];
    int c = 0;
#pragma unroll
    for (int k = 0; k < 8; k++) {
        v[k] = __ldcs(ar + k * 256 + t);
        c += (v[k].x != 0.f) + (v[k].y != 0.f) + (v[k].z != 0.f) + (v[k].w != 0.f);
    }

    int inc = c;
#pragma unroll
    for (int o = 1; o < 32; o <<= 1) {
        int y = __shfl_up_sync(FULLMASK, inc, o);
        if (lane >= o) inc += y;
    }
    if (lane == 31) wtot[wid] = inc;
    __syncthreads();
    if (t == 0) {
        int s = 0;
#pragma unroll
        for (int i = 0; i < 8; i++) { wbase[i] = s; s += wtot[i]; }
        g_rowcnt[row] = (s < MAXDEG) ? s : MAXDEG;
        g_dinv[row]   = rsqrtf((float)s + 1.0f + 1e-10f);
    }
    __syncthreads();

    int off = wbase[wid] + inc - c;
    int* cp = g_cols + row * MAXDEG;
#pragma unroll
    for (int k = 0; k < 8; k++) {
        int col0 = (k * 256 + t) * 4;
        if (v[k].x != 0.f) { if (off < MAXDEG) cp[off] = col0 + 0; off++; }
        if (v[k].y != 0.f) { if (off < MAXDEG) cp[off] = col0 + 1; off++; }
        if (v[k].z != 0.f) { if (off < MAXDEG) cp[off] = col0 + 2; off++; }
        if (v[k].w != 0.f) { if (off < MAXDEG) cp[off] = col0 + 3; off++; }
    }
}

// ---------------- G1 = dinv * (x @ W1) -----------------------------------------
__global__ void k_g1(const float* __restrict__ x, const float* __restrict__ W1) {
    __shared__ float w[FIN * FF];
    for (int i = threadIdx.x; i < FIN * FF; i += blockDim.x) w[i] = W1[i];
    __syncthreads();
    int warp = (blockIdx.x * blockDim.x + threadIdx.x) >> 5;
    int lane = threadIdx.x & 31;
    if (warp >= NN) return;
    float xv = (lane < FIN) ? x[warp * FIN + lane] : 0.f;
    float acc = 0.f;
#pragma unroll
    for (int f = 0; f < FIN; f++) {
        float xf = __shfl_sync(FULLMASK, xv, f);
        acc += xf * w[f * FF + lane];
    }
    g_G1[warp * FF + lane] = g_dinv[warp] * acc;
}

// ---------------- main SpMM: X1 = relu(dinv*(A_hat @ G1)); score1 --------------
__global__ void k_spmm_main(const float* __restrict__ s1) {
    __shared__ float sv[FF];
    if (threadIdx.x < FF) sv[threadIdx.x] = s1[threadIdx.x];
    __syncthreads();
    int warp = (blockIdx.x * blockDim.x + threadIdx.x) >> 5;
    int lane = threadIdx.x & 31;
    if (warp >= NN) return;
    int g = lane >> 3, fo = lane & 7;
    int cnt = g_rowcnt[warp];
    const int* cp = g_cols + warp * MAXDEG;
    const float4* G1v = reinterpret_cast<const float4*>(g_G1);

    float4 acc = make_float4(0.f, 0.f, 0.f, 0.f);
    if (g == 0) acc = G1v[warp * 8 + fo];    // identity (+I) term

    for (int k0 = 0; k0 < cnt; k0 += 32) {
        int kc = k0 + lane;
        int mycol = (kc < cnt) ? cp[kc] : -1;
#pragma unroll
        for (int s = 0; s < 8; s++) {
            int c = __shfl_sync(FULLMASK, mycol, s * 4 + g);
            if (c >= 0) {
                float4 tv = G1v[c * 8 + fo];
                acc.x += tv.x; acc.y += tv.y; acc.z += tv.z; acc.w += tv.w;
            }
        }
    }
#pragma unroll
    for (int o = 8; o <= 16; o <<= 1) {
        acc.x += __shfl_xor_sync(FULLMASK, acc.x, o);
        acc.y += __shfl_xor_sync(FULLMASK, acc.y, o);
        acc.z += __shfl_xor_sync(FULLMASK, acc.z, o);
        acc.w += __shfl_xor_sync(FULLMASK, acc.w, o);
    }
    float d = g_dinv[warp];
    acc.x = fmaxf(d * acc.x, 0.f); acc.y = fmaxf(d * acc.y, 0.f);
    acc.z = fmaxf(d * acc.z, 0.f); acc.w = fmaxf(d * acc.w, 0.f);
    if (g == 0) reinterpret_cast<float4*>(g_X1)[warp * 8 + fo] = acc;

    float s = acc.x * sv[fo * 4 + 0] + acc.y * sv[fo * 4 + 1] +
              acc.z * sv[fo * 4 + 2] + acc.w * sv[fo * 4 + 3];
    s += __shfl_down_sync(FULLMASK, s, 4);
    s += __shfl_down_sync(FULLMASK, s, 2);
    s += __shfl_down_sync(FULLMASK, s, 1);
    if (lane == 0) g_score1[warp] = s;
}

// ---------------- exact top-K set: radix select, all-parallel ------------------
// Register keys; warp-private histograms (plain adds via match_any leaders);
// threshold bin found by a PARALLEL 256-bin suffix scan (no serial walk).
__global__ void k_topk(int which) {
    const float* scores = which ? g_score2 : g_score1;
    int  n        = which ? KP1 : NN;
    int  K        = which ? KP2 : KP1;
    int* idx_out  = which ? g_idx2 : g_idx1;
    int* rank_out = which ? g_rank2 : g_rank1;

    __shared__ int histW[32 * 256];   // per-warp private histograms (32 KB)
    __shared__ int ssum[256];
    __shared__ int wagg[32];
    __shared__ int sh_prefix, sh_need, sh_bin;

    int t = threadIdx.x;
    int lane = t & 31, wid = t >> 5;
    int seg = n >> 10;                        // 8 (n=8192) or 4 (n=4096)

    unsigned u[8];
#pragma unroll
    for (int j = 0; j < 8; j++) {
        if (j < seg) {
            unsigned b = __float_as_uint(scores[t * seg + j]);
            u[j] = (b & 0x80000000u) ? ~b : (b | 0x80000000u);
        } else u[j] = 0u;
    }
    if (t == 0) { sh_prefix = 0; sh_need = K; }

    for (int shift = 24; shift >= 0; shift -= 8) {
        for (int i = t; i < 32 * 256; i += 1024) histW[i] = 0;
        __syncthreads();
        unsigned pfx = (unsigned)sh_prefix;
#pragma unroll
        for (int j = 0; j < 8; j++) {
            if (j >= seg) break;
            bool match = (shift == 24) ||
                         ((u[j] >> (shift + 8)) == (pfx >> (shift + 8)));
            int bin = match ? (int)((u[j] >> shift) & 255) : 300;
            unsigned mm = __match_any_sync(FULLMASK, bin);
            if (bin < 256 && lane == (__ffs(mm) - 1))
                histW[wid * 256 + bin] += __popc(mm);   // plain add, warp-private
        }
        __syncthreads();
        if (t < 256) {
            int s = 0;
#pragma unroll
            for (int w = 0; w < 32; w++) s += histW[w * 256 + t];
            ssum[t] = s;
        }
        __syncthreads();
        // parallel suffix sums: ssum[b] = sum_{j >= b} hist[j]  (Hillis-Steele)
#pragma unroll
        for (int off = 1; off < 256; off <<= 1) {
            int v = 0;
            if (t < 256) v = ssum[t] + ((t + off < 256) ? ssum[t + off] : 0);
            __syncthreads();
            if (t < 256) ssum[t] = v;
            __syncthreads();
        }
        if (t < 256) {
            int need = sh_need;
            int Sb = ssum[t];
            int Sn = (t < 255) ? ssum[t + 1] : 0;
            if (Sb >= need && Sn < need) sh_bin = t;   // unique b
        }
        __syncthreads();
        if (t == 0) {
            int b = sh_bin;
            int Sn = (b < 255) ? ssum[b + 1] : 0;
            sh_need   = sh_need - Sn;
            sh_prefix = sh_prefix | (b << shift);
        }
        __syncthreads();
    }
    unsigned T = (unsigned)sh_prefix;         // exact K-th largest key
    int need_eq = sh_need;                    // #(==T) to take, lowest indices

    int gt = 0, eq = 0;
#pragma unroll
    for (int j = 0; j < 8; j++) {
        if (j >= seg) break;
        gt += (u[j] > T); eq += (u[j] == T);
    }
    int packed = (gt << 16) | eq;
    int s = packed;
#pragma unroll
    for (int o = 1; o < 32; o <<= 1) {
        int y = __shfl_up_sync(FULLMASK, s, o);
        if (lane >= o) s += y;
    }
    if (lane == 31) wagg[wid] = s;
    __syncthreads();
    if (wid == 0) {
        int w = wagg[lane];
#pragma unroll
        for (int o = 1; o < 32; o <<= 1) {
            int y = __shfl_up_sync(FULLMASK, w, o);
            if (lane >= o) w += y;
        }
        wagg[lane] = w;
    }
    __syncthreads();
    int excl = s - packed + (wid ? wagg[wid - 1] : 0);
    int gtb = excl >> 16, eqb = excl & 0xffff;

#pragma unroll
    for (int j = 0; j < 8; j++) {
        if (j >= seg) break;
        int i = t * seg + j;
        bool isgt = (u[j] > T), iseq = (u[j] == T);
        bool sel  = isgt || (iseq && eqb < need_eq);
        int taken_eq = (eqb < need_eq) ? eqb : need_eq;
        int pos = gtb + taken_eq;
        if (sel) { rank_out[i] = pos; idx_out[pos] = i; }
        else       rank_out[i] = -1;
        gtb += isgt; eqb += iseq;
    }
}

// ---------------- sub-CSR build + dinvs + G2 (fused, batched MLP) --------------
__global__ void k_sub(const float* __restrict__ W2) {
    __shared__ float w[FF * FF];
    for (int i = threadIdx.x; i < FF * FF; i += blockDim.x) w[i] = W2[i];
    __syncthreads();
    int r = (blockIdx.x * blockDim.x + threadIdx.x) >> 5;
    int lane = threadIdx.x & 31;
    if (r >= KP1) return;
    int i = g_idx1[r];
    int cnt = g_rowcnt[i];
    const int* cp = g_cols + i * MAXDEG;
    int* sp = g_subcols + r * SUBMAX;
    unsigned lt = (1u << lane) - 1u;
    int nch = (cnt + 31) >> 5;

    int col[8], rk[8];
#pragma unroll
    for (int c = 0; c < 8; c++) {
        int k = c * 32 + lane;
        col[c] = (c < nch && k < cnt) ? cp[k] : -1;
    }
#pragma unroll
    for (int c = 0; c < 8; c++)
        rk[c] = (col[c] >= 0) ? g_rank1[col[c]] : -1;

    int wcnt = 0;
#pragma unroll
    for (int c = 0; c < 8; c++) {
        if (c >= nch) break;
        int ok = (rk[c] >= 0);
        unsigned m = __ballot_sync(FULLMASK, ok);
        if (ok) { int p = wcnt + __popc(m & lt); if (p < SUBMAX) sp[p] = rk[c]; }
        wcnt += __popc(m);
    }
    float di = rsqrtf((float)wcnt + 1.0f + 1e-10f);
    if (lane == 0) {
        g_subcnt[r] = (wcnt < SUBMAX) ? wcnt : SUBMAX;
        g_dinvs[r]  = di;
    }
    float xv = g_X1[i * FF + lane];
    float acc = 0.f;
#pragma unroll
    for (int f = 0; f < FF; f++) {
        float xf = __shfl_sync(FULLMASK, xv, f);
        acc += xf * w[f * FF + lane];
    }
    g_G2[r * FF + lane] = di * acc;
}

// ---------------- subgraph SpMM (vectorized, pre-filtered sub-CSR) -------------
__global__ void k_spmm_sub(int phase, const float* __restrict__ svec) {
    __shared__ float sv[FF];
    if (phase == 0 && threadIdx.x < FF) sv[threadIdx.x] = svec[threadIdx.x];
    __syncthreads();
    const float4* Gv = reinterpret_cast<const float4*>(phase ? g_G3 : g_G2);
    float4*       Xv = reinterpret_cast<float4*>(phase ? g_X3 : g_X2);
    int r = (blockIdx.x * blockDim.x + threadIdx.x) >> 5;
    int lane = threadIdx.x & 31;
    if (r >= KP1) return;
    int g = lane >> 3, fo = lane & 7;
    int cnt = g_subcnt[r];
    const int* sp = g_subcols + r * SUBMAX;

    float4 acc = make_float4(0.f, 0.f, 0.f, 0.f);
    if (g == 0) acc = Gv[r * 8 + fo];
    for (int k0 = 0; k0 < cnt; k0 += 32) {
        int kc = k0 + lane;
        int mycol = (kc < cnt) ? sp[kc] : -1;
#pragma unroll
        for (int s = 0; s < 8; s++) {
            int c = __shfl_sync(FULLMASK, mycol, s * 4 + g);
            if (c >= 0) {
                float4 tv = Gv[c * 8 + fo];
                acc.x += tv.x; acc.y += tv.y; acc.z += tv.z; acc.w += tv.w;
            }
        }
    }
#pragma unroll
    for (int o = 8; o <= 16; o <<= 1) {
        acc.x += __shfl_xor_sync(FULLMASK, acc.x, o);
        acc.y += __shfl_xor_sync(FULLMASK, acc.y, o);
        acc.z += __shfl_xor_sync(FULLMASK, acc.z, o);
        acc.w += __shfl_xor_sync(FULLMASK, acc.w, o);
    }
    float d = g_dinvs[r];
    acc.x = fmaxf(d * acc.x, 0.f); acc.y = fmaxf(d * acc.y, 0.f);
    acc.z = fmaxf(d * acc.z, 0.f); acc.w = fmaxf(d * acc.w, 0.f);
    if (g == 0) Xv[r * 8 + fo] = acc;
    if (phase == 0) {
        float s = acc.x * sv[fo * 4 + 0] + acc.y * sv[fo * 4 + 1] +
                  acc.z * sv[fo * 4 + 2] + acc.w * sv[fo * 4 + 3];
        s += __shfl_down_sync(FULLMASK, s, 4);
        s += __shfl_down_sync(FULLMASK, s, 2);
        s += __shfl_down_sync(FULLMASK, s, 1);
        if (lane == 0) g_score2[r] = s;
    }
}

// ---------------- G3 = (rank2>=0) ? dinvs*(X2@W3) : 0 --------------------------
__global__ void k_g3(const float* __restrict__ W3) {
    __shared__ float w[FF * FF];
    for (int i = threadIdx.x; i < FF * FF; i += blockDim.x) w[i] = W3[i];
    __syncthreads();
    int r = (blockIdx.x * blockDim.x + threadIdx.x) >> 5;
    int lane = threadIdx.x & 31;
    if (r >= KP1) return;
    if (g_rank2[r] < 0) { g_G3[r * FF + lane] = 0.f; return; }
    float xv = g_X2[r * FF + lane];
    float acc = 0.f;
#pragma unroll
    for (int f = 0; f < FF; f++) {
        float xf = __shfl_sync(FULLMASK, xv, f);
        acc += xf * w[f * FF + lane];
    }
    g_G3[r * FF + lane] = g_dinvs[r] * acc;
}

// ---------------- G4 = dinv * (unpool1(X3) @ W4) -------------------------------
__global__ void k_g4(const float* __restrict__ W4) {
    __shared__ float w[FF * 2];
    for (int i = threadIdx.x; i < FF * 2; i += blockDim.x) w[i] = W4[i];
    __syncthreads();
    int i = blockIdx.x * blockDim.x + threadIdx.x;
    if (i >= NN) return;
    int rr = g_rank1[i];
    float h0 = 0.f, h1 = 0.f;
    if (rr >= 0) {
        const float4* xr = reinterpret_cast<const float4*>(g_X3 + rr * FF);
#pragma unroll
        for (int q = 0; q < 8; q++) {
            float4 xv = xr[q];
            h0 += xv.x * w[(q * 4 + 0) * 2] + xv.y * w[(q * 4 + 1) * 2] +
                  xv.z * w[(q * 4 + 2) * 2] + xv.w * w[(q * 4 + 3) * 2];
            h1 += xv.x * w[(q * 4 + 0) * 2 + 1] + xv.y * w[(q * 4 + 1) * 2 + 1] +
                  xv.z * w[(q * 4 + 2) * 2 + 1] + xv.w * w[(q * 4 + 3) * 2 + 1];
        }
    }
    float d = g_dinv[i];
    g_G4[i] = make_float2(d * h0, d * h1);
}

// ---------------- final SpMM (F=2) + normalization + softmax -------------------
__global__ void k_final(float* __restrict__ out) {
    int warp = (blockIdx.x * blockDim.x + threadIdx.x) >> 5;
    int lane = threadIdx.x & 31;
    if (warp >= NN) return;
    int cnt = g_rowcnt[warp];
    const int* cp = g_cols + warp * MAXDEG;
    float a0 = 0.f, a1 = 0.f;
    for (int k = lane; k < cnt; k += 32) {
        float2 gv = g_G4[cp[k]];
        a0 += gv.x; a1 += gv.y;
    }
#pragma unroll
    for (int o = 16; o > 0; o >>= 1) {
        a0 += __shfl_down_sync(FULLMASK, a0, o);
        a1 += __shfl_down_sync(FULLMASK, a1, o);
    }
    if (lane == 0) {
        float2 gs = g_G4[warp];
        float d = g_dinv[warp];
        float y0 = d * (a0 + gs.x);
        float y1 = d * (a1 + gs.y);
        float m = fmaxf(y0, y1);
        float e0 = expf(y0 - m);
        float e1 = expf(y1 - m);
        float inv = 1.0f / (e0 + e1);
        out[warp * 2 + 0] = e0 * inv;
        out[warp * 2 + 1] = e1 * inv;
    }
}

// ---------------- launcher ----------------------------------------------------
extern "C" void kernel_launch(void* const* d_in, const int* in_sizes, int n_in,
                              void* d_out, int out_size) {
    (void)in_sizes; (void)n_in; (void)out_size;
    const float* x  = (const float*)d_in[0];
    const float* a  = (const float*)d_in[1];
    const float* W1 = (const float*)d_in[2];
    const float* W2 = (const float*)d_in[3];
    const float* W3 = (const float*)d_in[4];
    const float* W4 = (const float*)d_in[5];
    const float* s1 = (const float*)d_in[6];
    const float* s2 = (const float*)d_in[7];
    float* out = (float*)d_out;

    k_csr<<<NN, 256>>>(a);
    k_g1<<<NN / 8, 256>>>(x, W1);
    k_spmm_main<<<NN / 8, 256>>>(s1);
    k_topk<<<1, 1024>>>(0);          // 4th launch -> profiled slot
    k_sub<<<KP1 / 8, 256>>>(W2);
    k_spmm_sub<<<KP1 / 8, 256>>>(0, s2);
    k_topk<<<1, 1024>>>(1);
    k_g3<<<KP1 / 8, 256>>>(W3);
    k_spmm_sub<<<KP1 / 8, 256>>>(1, nullptr);
    k_g4<<<NN / 256, 256>>>(W4);
    k_final<<<NN / 8, 256>>>(out);
}